// round 10
// baseline (speedup 1.0000x reference)
#include <cuda_runtime.h>
#include <cstdint>
#include <cstddef>

// ---------------------------------------------------------------------------
// ModularLinear: out[t,b,k*OUT+o] = sum_i x[t,b,i] * W[sel[b,k],i,o] + bias[sel[b,k],o]
// 16 independent 1024^3 fp32 GEMMs.
// tcgen05 is unusable (harness compiles PTX at virtual arch compute_103, which
// rejects sm_103a-only instructions). sm_80+ path: mma.sync.m16n8k8.tf32 +
// cp.async, with RNA-rounded inputs for precision.
// ---------------------------------------------------------------------------

namespace mlcfg {
constexpr int T_   = 1024;
constexpr int B_   = 8;
constexpr int CIN  = 1024;
constexpr int COUT = 1024;
constexpr int NMOD = 16;
constexpr int KSEL = 2;

constexpr int TM = 128;           // CTA M tile
constexpr int TN = 128;           // CTA N tile
constexpr int KC = 16;            // K chunk (fp32) per pipeline stage
constexpr int NSTAGE = 4;
constexpr int NC = CIN / KC;      // 64 chunks

constexpr int KP = 24;            // padded row pitch in floats (16 data + 8 pad)
constexpr int TILE_FLOATS  = TM * KP;            // 3072 floats per operand tile
constexpr int STAGE_FLOATS = 2 * TILE_FLOATS;    // A then B
constexpr int STAGE_BYTES  = STAGE_FLOATS * 4;   // 24576
constexpr int SMEM_TOTAL   = NSTAGE * STAGE_BYTES;  // 98304
}  // namespace mlcfg

// Scratch (static device arrays are the sanctioned workaround for no-alloc).
__device__ __align__(16) float g_x [(size_t)mlcfg::T_ * mlcfg::B_ * mlcfg::CIN];     // 32 MB
__device__ __align__(16) float g_wt[(size_t)mlcfg::NMOD * mlcfg::COUT * mlcfg::CIN]; // 64 MB

// ---------------------------------------------------------------------------
// helpers
// ---------------------------------------------------------------------------
__device__ __forceinline__ uint32_t smem_u32(const void* p) {
    uint32_t a;
    asm("{ .reg .u64 t; cvta.to.shared.u64 t, %1; cvt.u32.u64 %0, t; }" : "=r"(a) : "l"(p));
    return a;
}

__device__ __forceinline__ void cp_async16(uint32_t saddr, const void* gptr) {
    asm volatile("cp.async.cg.shared.global [%0], [%1], 16;" :: "r"(saddr), "l"(gptr));
}
__device__ __forceinline__ void cp_commit() {
    asm volatile("cp.async.commit_group;" ::: "memory");
}
__device__ __forceinline__ void cp_wait_dyn(int n) {
    if (n >= 2)      asm volatile("cp.async.wait_group 2;" ::: "memory");
    else if (n == 1) asm volatile("cp.async.wait_group 1;" ::: "memory");
    else             asm volatile("cp.async.wait_group 0;" ::: "memory");
}

__device__ __forceinline__ float to_tf32_rna(float f) {
    uint32_t u;
    asm("cvt.rna.tf32.f32 %0, %1;" : "=r"(u) : "f"(f));
    return __uint_as_float(u);
}

// m16n8k8 tf32 MMA. A row-major frag {a0..a3}, B col-major frag {b0,b1}, fp32 acc.
__device__ __forceinline__ void mma_tf32(float& d0, float& d1, float& d2, float& d3,
                                         float a0, float a1, float a2, float a3,
                                         float b0, float b1) {
    asm volatile(
        "mma.sync.aligned.m16n8k8.row.col.f32.tf32.tf32.f32 "
        "{%0,%1,%2,%3}, {%4,%5,%6,%7}, {%8,%9}, {%0,%1,%2,%3};"
        : "+f"(d0), "+f"(d1), "+f"(d2), "+f"(d3)
        : "r"(__float_as_uint(a0)), "r"(__float_as_uint(a1)),
          "r"(__float_as_uint(a2)), "r"(__float_as_uint(a3)),
          "r"(__float_as_uint(b0)), "r"(__float_as_uint(b1)));
}

// ---------------------------------------------------------------------------
// Prologue 1: RNA-round x -> g_x with k-interleave inside each 8-float group.
// Position map pos(j) = 2*(j&3) + (j>>2): smem pos 2t holds k=t, pos 2t+1
// holds k=t+4 -> a thread's frag pair (col tig, col tig+4) is one LDS.64.
// ---------------------------------------------------------------------------
__global__ void ml_round_x_kernel(const float4* __restrict__ x, int ngrp) {
    int i = blockIdx.x * blockDim.x + threadIdx.x;   // one 8-float group per thread
    if (i >= ngrp) return;
    float4 lo = x[2 * i];
    float4 hi = x[2 * i + 1];
    float4 o0, o1;
    o0.x = to_tf32_rna(lo.x);  o0.y = to_tf32_rna(hi.x);
    o0.z = to_tf32_rna(lo.y);  o0.w = to_tf32_rna(hi.y);
    o1.x = to_tf32_rna(lo.z);  o1.y = to_tf32_rna(hi.z);
    o1.z = to_tf32_rna(lo.w);  o1.w = to_tf32_rna(hi.w);
    reinterpret_cast<float4*>(g_x)[2 * i]     = o0;
    reinterpret_cast<float4*>(g_x)[2 * i + 1] = o1;
}

// ---------------------------------------------------------------------------
// Prologue 2: transpose + round W[e][i][o] -> g_wt[e][o][pos(i)] (K-major,
// k-interleaved to match g_x).
// R8 BUG FIXED HERE: the permute must act on (tx & 7); previously (tx >> 2)
// leaked bits 3-4 of tx into the low field, corrupting 3/4 of every W row.
// ---------------------------------------------------------------------------
__global__ void ml_transpose_w_kernel(const float* __restrict__ W) {
    using namespace mlcfg;
    __shared__ float tile[32][33];
    int e  = blockIdx.z;
    int o0 = blockIdx.x * 32;
    int i0 = blockIdx.y * 32;
    int tx = threadIdx.x, ty = threadIdx.y;   // 32 x 8
    const float* Wb  = W    + (size_t)e * CIN * COUT;
    float*       Wtb = g_wt + (size_t)e * COUT * CIN;
#pragma unroll
    for (int rr = 0; rr < 32; rr += 8)
        tile[ty + rr][tx] = Wb[(size_t)(i0 + ty + rr) * COUT + o0 + tx];
    __syncthreads();
    const int j     = tx & 7;                                  // k within group of 8
    const int iperm = (tx & ~7) | (2 * (j & 3) + (j >> 2));    // k-interleave (FIXED)
#pragma unroll
    for (int rr = 0; rr < 32; rr += 8)
        Wtb[(size_t)(o0 + ty + rr) * CIN + i0 + iperm] = to_tf32_rna(tile[tx][ty + rr]);
}

// ---------------------------------------------------------------------------
// Main GEMM. CTA: 128x128 output tile of one (b,k) expert GEMM.
// 256 threads = 8 warps in a 2(M) x 4(N) grid; warp tile 64x32.
// 4-stage cp.async pipeline, KC=16 per stage.
// ---------------------------------------------------------------------------
__device__ __forceinline__ void ml_load_stage(uint32_t sa, uint32_t sbb,
                                              const float* __restrict__ ga,
                                              const float* __restrict__ gb,
                                              int tid) {
    using namespace mlcfg;
    // Each operand tile: 128 rows x 64B data (96B pitch) = 512 x 16B chunks.
#pragma unroll
    for (int j = 0; j < 2; ++j) {
        int idx = tid + j * 256;
        int r = idx >> 2, ch = idx & 3;
        cp_async16(sa + r * (KP * 4) + ch * 16, ga + (size_t)r * (B_ * CIN) + ch * 4);
    }
#pragma unroll
    for (int j = 0; j < 2; ++j) {
        int idx = tid + j * 256;
        int r = idx >> 2, ch = idx & 3;
        cp_async16(sbb + r * (KP * 4) + ch * 16, gb + (size_t)r * CIN + ch * 4);
    }
    cp_commit();
}

__global__ void __launch_bounds__(256)
ml_gemm_kernel(const int* __restrict__ sel32,
               const float* __restrict__ bias,
               float* __restrict__ out) {
    using namespace mlcfg;
    extern __shared__ float smf[];
    const uint32_t sb = smem_u32(smf);
    const int tid = threadIdx.x;
    const int wid = tid >> 5;
    const int lane = tid & 31;
    const int g   = lane >> 2;       // groupID   (0..7)
    const int tig = lane & 3;        // thread-in-group (0..3)
    const int warp_m = wid >> 2;     // 0..1  -> 64 rows each
    const int warp_n = wid & 3;      // 0..3  -> 32 cols each

    const int nt_ = blockIdx.x;      // 0..7 -> o0
    const int mt_ = blockIdx.y;      // 0..7 -> t0
    const int p   = blockIdx.z;      // 0..15 -> (b, k)
    const int b   = p / KSEL;
    const int kk  = p - b * KSEL;
    const int t0  = mt_ * TM;
    const int o0  = nt_ * TN;

    // selection may be int64 (odd int32 words all zero, values in [0,16)) or int32
    bool is64 = true;
#pragma unroll
    for (int j = 1; j < 16; j += 2) is64 &= (sel32[j] == 0);
    const int sidx = b * KSEL + kk;
    const int sel  = (is64 ? sel32[2 * sidx] : sel32[sidx]) & (NMOD - 1);

    const float* A0 = g_x  + ((size_t)t0 * B_ + b) * CIN;        // row stride B_*CIN
    const float* B0 = g_wt + ((size_t)sel * COUT + o0) * CIN;    // row stride CIN

    // prologue: fill stages 0..NSTAGE-2
#pragma unroll
    for (int s = 0; s < NSTAGE - 1; ++s)
        ml_load_stage(sb + s * STAGE_BYTES,
                      sb + s * STAGE_BYTES + TILE_FLOATS * 4,
                      A0 + s * KC, B0 + s * KC, tid);

    float d[4][4][4];
#pragma unroll
    for (int mt = 0; mt < 4; ++mt)
#pragma unroll
        for (int nt = 0; nt < 4; ++nt)
#pragma unroll
            for (int r = 0; r < 4; ++r) d[mt][nt][r] = 0.0f;

    // per-thread fragment base offsets (floats, within a stage)
    const int aoff = (warp_m * 64 + g) * KP + 2 * tig;
    const int boff = TILE_FLOATS + (warp_n * 32 + g) * KP + 2 * tig;

    for (int c = 0; c < NC; ++c) {
        const int left = NC - 1 - c;
        cp_wait_dyn(left < NSTAGE - 2 ? left : NSTAGE - 2);   // chunk c resident
        __syncthreads();

        const int cn = c + NSTAGE - 1;
        if (cn < NC) {
            const int sn = cn & (NSTAGE - 1);
            ml_load_stage(sb + sn * STAGE_BYTES,
                          sb + sn * STAGE_BYTES + TILE_FLOATS * 4,
                          A0 + cn * KC, B0 + cn * KC, tid);
        }

        const float* st = smf + (c & (NSTAGE - 1)) * STAGE_FLOATS;
#pragma unroll
        for (int s2 = 0; s2 < 2; ++s2) {                      // two k=8 slices
            const float* As = st + aoff + 8 * s2;
            const float* Bs = st + boff + 8 * s2;
            float2 a[4][2], bb[4];
#pragma unroll
            for (int mt = 0; mt < 4; ++mt) {
                a[mt][0] = *reinterpret_cast<const float2*>(As + mt * (16 * KP));
                a[mt][1] = *reinterpret_cast<const float2*>(As + mt * (16 * KP) + 8 * KP);
            }
#pragma unroll
            for (int nt = 0; nt < 4; ++nt)
                bb[nt] = *reinterpret_cast<const float2*>(Bs + nt * (8 * KP));
#pragma unroll
            for (int mt = 0; mt < 4; ++mt)
#pragma unroll
                for (int nt = 0; nt < 4; ++nt)
                    mma_tf32(d[mt][nt][0], d[mt][nt][1], d[mt][nt][2], d[mt][nt][3],
                             a[mt][0].x, a[mt][1].x, a[mt][0].y, a[mt][1].y,
                             bb[nt].x, bb[nt].y);
        }
    }

    // epilogue: + bias, fp32 stores
    const float* brow = bias + (size_t)sel * COUT + o0 + warp_n * 32 + 2 * tig;
    float* obase = out + (size_t)kk * COUT + o0 + warp_n * 32 + 2 * tig;
    constexpr size_t ROWSTRIDE = (size_t)mlcfg::B_ * mlcfg::KSEL * mlcfg::COUT;
#pragma unroll
    for (int nt = 0; nt < 4; ++nt) {
        const float2 bv = *reinterpret_cast<const float2*>(brow + nt * 8);
#pragma unroll
        for (int mt = 0; mt < 4; ++mt) {
            const int row = t0 + warp_m * 64 + mt * 16 + g;
            float* orow = obase + ((size_t)row * B_ + b) * (KSEL * COUT) + nt * 8;
            float2 v0, v1;
            v0.x = d[mt][nt][0] + bv.x;  v0.y = d[mt][nt][1] + bv.y;
            v1.x = d[mt][nt][2] + bv.x;  v1.y = d[mt][nt][3] + bv.y;
            *reinterpret_cast<float2*>(orow) = v0;
            *reinterpret_cast<float2*>(orow + 8 * ROWSTRIDE) = v1;   // row + 8
        }
    }
}

// ---------------------------------------------------------------------------
// Launch
// ---------------------------------------------------------------------------
extern "C" void kernel_launch(void* const* d_in, const int* in_sizes, int n_in,
                              void* d_out, int out_size) {
    using namespace mlcfg;
    const float* x    = (const float*)d_in[0];
    const int*   sel  = (const int*)  d_in[1];   // int32 view; int64 auto-detected
    const float* w    = (const float*)d_in[2];
    const float* bias = (const float*)d_in[3];
    float*       out  = (float*)d_out;
    (void)in_sizes; (void)n_in; (void)out_size;

    cudaFuncSetAttribute(ml_gemm_kernel,
                         cudaFuncAttributeMaxDynamicSharedMemorySize, SMEM_TOTAL);

    const int ngrp = T_ * B_ * CIN / 8;          // 8-float groups
    ml_round_x_kernel<<<(ngrp + 255) / 256, 256>>>(
        reinterpret_cast<const float4*>(x), ngrp);

    ml_transpose_w_kernel<<<dim3(COUT / 32, CIN / 32, NMOD), dim3(32, 8)>>>(w);

    ml_gemm_kernel<<<dim3(COUT / TN, T_ / TM, B_ * KSEL), 256, SMEM_TOTAL>>>(
        sel, bias, out);
}

// round 11
// speedup vs baseline: 1.0014x; 1.0014x over previous
#include <cuda_runtime.h>
#include <cstdint>
#include <cstddef>

// ---------------------------------------------------------------------------
// ModularLinear: out[t,b,k*OUT+o] = sum_i x[t,b,i] * W[sel[b,k],i,o] + bias[sel[b,k],o]
// 16 independent 1024^3 fp32 GEMMs.
// tcgen05 is unusable (harness compiles PTX at virtual arch compute_103, which
// rejects sm_103a-only instructions). sm_80+ path: mma.sync.m16n8k8.tf32 +
// cp.async, with RNA-rounded inputs for precision.
// ---------------------------------------------------------------------------

namespace mlcfg {
constexpr int T_   = 1024;
constexpr int B_   = 8;
constexpr int CIN  = 1024;
constexpr int COUT = 1024;
constexpr int NMOD = 16;
constexpr int KSEL = 2;

constexpr int TM = 128;           // CTA M tile
constexpr int TN = 128;           // CTA N tile
constexpr int KC = 16;            // K chunk (fp32) per pipeline stage
constexpr int NSTAGE = 4;
constexpr int NC = CIN / KC;      // 64 chunks

constexpr int KP = 24;            // padded row pitch in floats (16 data + 8 pad)
constexpr int TILE_FLOATS  = TM * KP;            // 3072 floats per operand tile
constexpr int STAGE_FLOATS = 2 * TILE_FLOATS;    // A then B
constexpr int STAGE_BYTES  = STAGE_FLOATS * 4;   // 24576
constexpr int SMEM_TOTAL   = NSTAGE * STAGE_BYTES;  // 98304
}  // namespace mlcfg

// Scratch (static device arrays are the sanctioned workaround for no-alloc).
__device__ __align__(16) float g_x [(size_t)mlcfg::T_ * mlcfg::B_ * mlcfg::CIN];     // 32 MB
__device__ __align__(16) float g_wt[(size_t)mlcfg::NMOD * mlcfg::COUT * mlcfg::CIN]; // 64 MB

// ---------------------------------------------------------------------------
// helpers
// ---------------------------------------------------------------------------
__device__ __forceinline__ uint32_t smem_u32(const void* p) {
    uint32_t a;
    asm("{ .reg .u64 t; cvta.to.shared.u64 t, %1; cvt.u32.u64 %0, t; }" : "=r"(a) : "l"(p));
    return a;
}

__device__ __forceinline__ void cp_async16(uint32_t saddr, const void* gptr) {
    asm volatile("cp.async.cg.shared.global [%0], [%1], 16;" :: "r"(saddr), "l"(gptr));
}
__device__ __forceinline__ void cp_commit() {
    asm volatile("cp.async.commit_group;" ::: "memory");
}
__device__ __forceinline__ void cp_wait_dyn(int n) {
    if (n >= 2)      asm volatile("cp.async.wait_group 2;" ::: "memory");
    else if (n == 1) asm volatile("cp.async.wait_group 1;" ::: "memory");
    else             asm volatile("cp.async.wait_group 0;" ::: "memory");
}

__device__ __forceinline__ float to_tf32_rna(float f) {
    uint32_t u;
    asm("cvt.rna.tf32.f32 %0, %1;" : "=r"(u) : "f"(f));
    return __uint_as_float(u);
}

// m16n8k8 tf32 MMA. A row-major frag {a0..a3}, B col-major frag {b0,b1}, fp32 acc.
__device__ __forceinline__ void mma_tf32(float& d0, float& d1, float& d2, float& d3,
                                         float a0, float a1, float a2, float a3,
                                         float b0, float b1) {
    asm volatile(
        "mma.sync.aligned.m16n8k8.row.col.f32.tf32.tf32.f32 "
        "{%0,%1,%2,%3}, {%4,%5,%6,%7}, {%8,%9}, {%0,%1,%2,%3};"
        : "+f"(d0), "+f"(d1), "+f"(d2), "+f"(d3)
        : "r"(__float_as_uint(a0)), "r"(__float_as_uint(a1)),
          "r"(__float_as_uint(a2)), "r"(__float_as_uint(a3)),
          "r"(__float_as_uint(b0)), "r"(__float_as_uint(b1)));
}

// ---------------------------------------------------------------------------
// Prologue 1: RNA-round x -> g_x with k-interleave inside each 8-float group.
// Position map pos(j) = 2*(j&3) + (j>>2): smem pos 2t holds k=t, pos 2t+1
// holds k=t+4 -> a thread's frag pair (col tig, col tig+4) is one LDS.64.
// ---------------------------------------------------------------------------
__global__ void ml_round_x_kernel(const float4* __restrict__ x, int ngrp) {
    int i = blockIdx.x * blockDim.x + threadIdx.x;   // one 8-float group per thread
    if (i >= ngrp) return;
    float4 lo = x[2 * i];
    float4 hi = x[2 * i + 1];
    float4 o0, o1;
    o0.x = to_tf32_rna(lo.x);  o0.y = to_tf32_rna(hi.x);
    o0.z = to_tf32_rna(lo.y);  o0.w = to_tf32_rna(hi.y);
    o1.x = to_tf32_rna(lo.z);  o1.y = to_tf32_rna(hi.z);
    o1.z = to_tf32_rna(lo.w);  o1.w = to_tf32_rna(hi.w);
    reinterpret_cast<float4*>(g_x)[2 * i]     = o0;
    reinterpret_cast<float4*>(g_x)[2 * i + 1] = o1;
}

// ---------------------------------------------------------------------------
// Prologue 2: transpose + round W[e][i][o] -> g_wt[e][o][pos(i)] (K-major,
// k-interleaved to match g_x).
// R8 BUG FIXED HERE: the permute must act on (tx & 7); previously (tx >> 2)
// leaked bits 3-4 of tx into the low field, corrupting 3/4 of every W row.
// ---------------------------------------------------------------------------
__global__ void ml_transpose_w_kernel(const float* __restrict__ W) {
    using namespace mlcfg;
    __shared__ float tile[32][33];
    int e  = blockIdx.z;
    int o0 = blockIdx.x * 32;
    int i0 = blockIdx.y * 32;
    int tx = threadIdx.x, ty = threadIdx.y;   // 32 x 8
    const float* Wb  = W    + (size_t)e * CIN * COUT;
    float*       Wtb = g_wt + (size_t)e * COUT * CIN;
#pragma unroll
    for (int rr = 0; rr < 32; rr += 8)
        tile[ty + rr][tx] = Wb[(size_t)(i0 + ty + rr) * COUT + o0 + tx];
    __syncthreads();
    const int j     = tx & 7;                                  // k within group of 8
    const int iperm = (tx & ~7) | (2 * (j & 3) + (j >> 2));    // k-interleave (FIXED)
#pragma unroll
    for (int rr = 0; rr < 32; rr += 8)
        Wtb[(size_t)(o0 + ty + rr) * CIN + i0 + iperm] = to_tf32_rna(tile[tx][ty + rr]);
}

// ---------------------------------------------------------------------------
// Main GEMM. CTA: 128x128 output tile of one (b,k) expert GEMM.
// 256 threads = 8 warps in a 2(M) x 4(N) grid; warp tile 64x32.
// 4-stage cp.async pipeline, KC=16 per stage.
// ---------------------------------------------------------------------------
__device__ __forceinline__ void ml_load_stage(uint32_t sa, uint32_t sbb,
                                              const float* __restrict__ ga,
                                              const float* __restrict__ gb,
                                              int tid) {
    using namespace mlcfg;
    // Each operand tile: 128 rows x 64B data (96B pitch) = 512 x 16B chunks.
#pragma unroll
    for (int j = 0; j < 2; ++j) {
        int idx = tid + j * 256;
        int r = idx >> 2, ch = idx & 3;
        cp_async16(sa + r * (KP * 4) + ch * 16, ga + (size_t)r * (B_ * CIN) + ch * 4);
    }
#pragma unroll
    for (int j = 0; j < 2; ++j) {
        int idx = tid + j * 256;
        int r = idx >> 2, ch = idx & 3;
        cp_async16(sbb + r * (KP * 4) + ch * 16, gb + (size_t)r * CIN + ch * 4);
    }
    cp_commit();
}

__global__ void __launch_bounds__(256)
ml_gemm_kernel(const int* __restrict__ sel32,
               const float* __restrict__ bias,
               float* __restrict__ out) {
    using namespace mlcfg;
    extern __shared__ float smf[];
    const uint32_t sb = smem_u32(smf);
    const int tid = threadIdx.x;
    const int wid = tid >> 5;
    const int lane = tid & 31;
    const int g   = lane >> 2;       // groupID   (0..7)
    const int tig = lane & 3;        // thread-in-group (0..3)
    const int warp_m = wid >> 2;     // 0..1  -> 64 rows each
    const int warp_n = wid & 3;      // 0..3  -> 32 cols each

    const int nt_ = blockIdx.x;      // 0..7 -> o0
    const int mt_ = blockIdx.y;      // 0..7 -> t0
    const int p   = blockIdx.z;      // 0..15 -> (b, k)
    const int b   = p / KSEL;
    const int kk  = p - b * KSEL;
    const int t0  = mt_ * TM;
    const int o0  = nt_ * TN;

    // selection may be int64 (odd int32 words all zero, values in [0,16)) or int32
    bool is64 = true;
#pragma unroll
    for (int j = 1; j < 16; j += 2) is64 &= (sel32[j] == 0);
    const int sidx = b * KSEL + kk;
    const int sel  = (is64 ? sel32[2 * sidx] : sel32[sidx]) & (NMOD - 1);

    const float* A0 = g_x  + ((size_t)t0 * B_ + b) * CIN;        // row stride B_*CIN
    const float* B0 = g_wt + ((size_t)sel * COUT + o0) * CIN;    // row stride CIN

    // prologue: fill stages 0..NSTAGE-2
#pragma unroll
    for (int s = 0; s < NSTAGE - 1; ++s)
        ml_load_stage(sb + s * STAGE_BYTES,
                      sb + s * STAGE_BYTES + TILE_FLOATS * 4,
                      A0 + s * KC, B0 + s * KC, tid);

    float d[4][4][4];
#pragma unroll
    for (int mt = 0; mt < 4; ++mt)
#pragma unroll
        for (int nt = 0; nt < 4; ++nt)
#pragma unroll
            for (int r = 0; r < 4; ++r) d[mt][nt][r] = 0.0f;

    // per-thread fragment base offsets (floats, within a stage)
    const int aoff = (warp_m * 64 + g) * KP + 2 * tig;
    const int boff = TILE_FLOATS + (warp_n * 32 + g) * KP + 2 * tig;

    for (int c = 0; c < NC; ++c) {
        const int left = NC - 1 - c;
        cp_wait_dyn(left < NSTAGE - 2 ? left : NSTAGE - 2);   // chunk c resident
        __syncthreads();

        const int cn = c + NSTAGE - 1;
        if (cn < NC) {
            const int sn = cn & (NSTAGE - 1);
            ml_load_stage(sb + sn * STAGE_BYTES,
                          sb + sn * STAGE_BYTES + TILE_FLOATS * 4,
                          A0 + cn * KC, B0 + cn * KC, tid);
        }

        const float* st = smf + (c & (NSTAGE - 1)) * STAGE_FLOATS;
#pragma unroll
        for (int s2 = 0; s2 < 2; ++s2) {                      // two k=8 slices
            const float* As = st + aoff + 8 * s2;
            const float* Bs = st + boff + 8 * s2;
            float2 a[4][2], bb[4];
#pragma unroll
            for (int mt = 0; mt < 4; ++mt) {
                a[mt][0] = *reinterpret_cast<const float2*>(As + mt * (16 * KP));
                a[mt][1] = *reinterpret_cast<const float2*>(As + mt * (16 * KP) + 8 * KP);
            }
#pragma unroll
            for (int nt = 0; nt < 4; ++nt)
                bb[nt] = *reinterpret_cast<const float2*>(Bs + nt * (8 * KP));
#pragma unroll
            for (int mt = 0; mt < 4; ++mt)
#pragma unroll
                for (int nt = 0; nt < 4; ++nt)
                    mma_tf32(d[mt][nt][0], d[mt][nt][1], d[mt][nt][2], d[mt][nt][3],
                             a[mt][0].x, a[mt][1].x, a[mt][0].y, a[mt][1].y,
                             bb[nt].x, bb[nt].y);
        }
    }

    // epilogue: + bias, fp32 stores
    const float* brow = bias + (size_t)sel * COUT + o0 + warp_n * 32 + 2 * tig;
    float* obase = out + (size_t)kk * COUT + o0 + warp_n * 32 + 2 * tig;
    constexpr size_t ROWSTRIDE = (size_t)mlcfg::B_ * mlcfg::KSEL * mlcfg::COUT;
#pragma unroll
    for (int nt = 0; nt < 4; ++nt) {
        const float2 bv = *reinterpret_cast<const float2*>(brow + nt * 8);
#pragma unroll
        for (int mt = 0; mt < 4; ++mt) {
            const int row = t0 + warp_m * 64 + mt * 16 + g;
            float* orow = obase + ((size_t)row * B_ + b) * (KSEL * COUT) + nt * 8;
            float2 v0, v1;
            v0.x = d[mt][nt][0] + bv.x;  v0.y = d[mt][nt][1] + bv.y;
            v1.x = d[mt][nt][2] + bv.x;  v1.y = d[mt][nt][3] + bv.y;
            *reinterpret_cast<float2*>(orow) = v0;
            *reinterpret_cast<float2*>(orow + 8 * ROWSTRIDE) = v1;   // row + 8
        }
    }
}

// ---------------------------------------------------------------------------
// Launch
// ---------------------------------------------------------------------------
extern "C" void kernel_launch(void* const* d_in, const int* in_sizes, int n_in,
                              void* d_out, int out_size) {
    using namespace mlcfg;
    const float* x    = (const float*)d_in[0];
    const int*   sel  = (const int*)  d_in[1];   // int32 view; int64 auto-detected
    const float* w    = (const float*)d_in[2];
    const float* bias = (const float*)d_in[3];
    float*       out  = (float*)d_out;
    (void)in_sizes; (void)n_in; (void)out_size;

    cudaFuncSetAttribute(ml_gemm_kernel,
                         cudaFuncAttributeMaxDynamicSharedMemorySize, SMEM_TOTAL);

    const int ngrp = T_ * B_ * CIN / 8;          // 8-float groups
    ml_round_x_kernel<<<(ngrp + 255) / 256, 256>>>(
        reinterpret_cast<const float4*>(x), ngrp);

    ml_transpose_w_kernel<<<dim3(COUT / 32, CIN / 32, NMOD), dim3(32, 8)>>>(w);

    ml_gemm_kernel<<<dim3(COUT / TN, T_ / TM, B_ * KSEL), 256, SMEM_TOTAL>>>(
        sel, bias, out);
}

// round 12
// speedup vs baseline: 1.0024x; 1.0010x over previous
#include <cuda_runtime.h>
#include <cstdint>
#include <cstddef>

// ---------------------------------------------------------------------------
// ModularLinear: out[t,b,k*OUT+o] = sum_i x[t,b,i] * W[sel[b,k],i,o] + bias[sel[b,k],o]
// 16 independent 1024^3 fp32 GEMMs.
// tcgen05 is unusable (harness compiles PTX at virtual arch compute_103, which
// rejects sm_103a-only instructions). sm_80+ path: mma.sync.m16n8k8.tf32 +
// cp.async, with RNA-rounded inputs for precision.
// ---------------------------------------------------------------------------

namespace mlcfg {
constexpr int T_   = 1024;
constexpr int B_   = 8;
constexpr int CIN  = 1024;
constexpr int COUT = 1024;
constexpr int NMOD = 16;
constexpr int KSEL = 2;

constexpr int TM = 128;           // CTA M tile
constexpr int TN = 128;           // CTA N tile
constexpr int KC = 16;            // K chunk (fp32) per pipeline stage
constexpr int NSTAGE = 4;
constexpr int NC = CIN / KC;      // 64 chunks

constexpr int KP = 24;            // padded row pitch in floats (16 data + 8 pad)
constexpr int TILE_FLOATS  = TM * KP;            // 3072 floats per operand tile
constexpr int STAGE_FLOATS = 2 * TILE_FLOATS;    // A then B
constexpr int STAGE_BYTES  = STAGE_FLOATS * 4;   // 24576
constexpr int SMEM_TOTAL   = NSTAGE * STAGE_BYTES;  // 98304
}  // namespace mlcfg

// Scratch (static device arrays are the sanctioned workaround for no-alloc).
__device__ __align__(16) float g_x [(size_t)mlcfg::T_ * mlcfg::B_ * mlcfg::CIN];     // 32 MB
__device__ __align__(16) float g_wt[(size_t)mlcfg::NMOD * mlcfg::COUT * mlcfg::CIN]; // 64 MB

// ---------------------------------------------------------------------------
// helpers
// ---------------------------------------------------------------------------
__device__ __forceinline__ uint32_t smem_u32(const void* p) {
    uint32_t a;
    asm("{ .reg .u64 t; cvta.to.shared.u64 t, %1; cvt.u32.u64 %0, t; }" : "=r"(a) : "l"(p));
    return a;
}

__device__ __forceinline__ void cp_async16(uint32_t saddr, const void* gptr) {
    asm volatile("cp.async.cg.shared.global [%0], [%1], 16;" :: "r"(saddr), "l"(gptr));
}
__device__ __forceinline__ void cp_commit() {
    asm volatile("cp.async.commit_group;" ::: "memory");
}
__device__ __forceinline__ void cp_wait_dyn(int n) {
    if (n >= 2)      asm volatile("cp.async.wait_group 2;" ::: "memory");
    else if (n == 1) asm volatile("cp.async.wait_group 1;" ::: "memory");
    else             asm volatile("cp.async.wait_group 0;" ::: "memory");
}

__device__ __forceinline__ float to_tf32_rna(float f) {
    uint32_t u;
    asm("cvt.rna.tf32.f32 %0, %1;" : "=r"(u) : "f"(f));
    return __uint_as_float(u);
}

// m16n8k8 tf32 MMA. A row-major frag {a0..a3}, B col-major frag {b0,b1}, fp32 acc.
__device__ __forceinline__ void mma_tf32(float& d0, float& d1, float& d2, float& d3,
                                         float a0, float a1, float a2, float a3,
                                         float b0, float b1) {
    asm volatile(
        "mma.sync.aligned.m16n8k8.row.col.f32.tf32.tf32.f32 "
        "{%0,%1,%2,%3}, {%4,%5,%6,%7}, {%8,%9}, {%0,%1,%2,%3};"
        : "+f"(d0), "+f"(d1), "+f"(d2), "+f"(d3)
        : "r"(__float_as_uint(a0)), "r"(__float_as_uint(a1)),
          "r"(__float_as_uint(a2)), "r"(__float_as_uint(a3)),
          "r"(__float_as_uint(b0)), "r"(__float_as_uint(b1)));
}

// ---------------------------------------------------------------------------
// Prologue 1: RNA-round x -> g_x with k-interleave inside each 8-float group.
// Position map pos(j) = 2*(j&3) + (j>>2): smem pos 2t holds k=t, pos 2t+1
// holds k=t+4 -> a thread's frag pair (col tig, col tig+4) is one LDS.64.
// ---------------------------------------------------------------------------
__global__ void ml_round_x_kernel(const float4* __restrict__ x, int ngrp) {
    int i = blockIdx.x * blockDim.x + threadIdx.x;   // one 8-float group per thread
    if (i >= ngrp) return;
    float4 lo = x[2 * i];
    float4 hi = x[2 * i + 1];
    float4 o0, o1;
    o0.x = to_tf32_rna(lo.x);  o0.y = to_tf32_rna(hi.x);
    o0.z = to_tf32_rna(lo.y);  o0.w = to_tf32_rna(hi.y);
    o1.x = to_tf32_rna(lo.z);  o1.y = to_tf32_rna(hi.z);
    o1.z = to_tf32_rna(lo.w);  o1.w = to_tf32_rna(hi.w);
    reinterpret_cast<float4*>(g_x)[2 * i]     = o0;
    reinterpret_cast<float4*>(g_x)[2 * i + 1] = o1;
}

// ---------------------------------------------------------------------------
// Prologue 2: transpose + round W[e][i][o] -> g_wt[e][o][pos(i)] (K-major,
// k-interleaved to match g_x).
// R8 BUG FIXED HERE: the permute must act on (tx & 7); previously (tx >> 2)
// leaked bits 3-4 of tx into the low field, corrupting 3/4 of every W row.
// ---------------------------------------------------------------------------
__global__ void ml_transpose_w_kernel(const float* __restrict__ W) {
    using namespace mlcfg;
    __shared__ float tile[32][33];
    int e  = blockIdx.z;
    int o0 = blockIdx.x * 32;
    int i0 = blockIdx.y * 32;
    int tx = threadIdx.x, ty = threadIdx.y;   // 32 x 8
    const float* Wb  = W    + (size_t)e * CIN * COUT;
    float*       Wtb = g_wt + (size_t)e * COUT * CIN;
#pragma unroll
    for (int rr = 0; rr < 32; rr += 8)
        tile[ty + rr][tx] = Wb[(size_t)(i0 + ty + rr) * COUT + o0 + tx];
    __syncthreads();
    const int j     = tx & 7;                                  // k within group of 8
    const int iperm = (tx & ~7) | (2 * (j & 3) + (j >> 2));    // k-interleave (FIXED)
#pragma unroll
    for (int rr = 0; rr < 32; rr += 8)
        Wtb[(size_t)(o0 + ty + rr) * CIN + i0 + iperm] = to_tf32_rna(tile[tx][ty + rr]);
}

// ---------------------------------------------------------------------------
// Main GEMM. CTA: 128x128 output tile of one (b,k) expert GEMM.
// 256 threads = 8 warps in a 2(M) x 4(N) grid; warp tile 64x32.
// 4-stage cp.async pipeline, KC=16 per stage.
// ---------------------------------------------------------------------------
__device__ __forceinline__ void ml_load_stage(uint32_t sa, uint32_t sbb,
                                              const float* __restrict__ ga,
                                              const float* __restrict__ gb,
                                              int tid) {
    using namespace mlcfg;
    // Each operand tile: 128 rows x 64B data (96B pitch) = 512 x 16B chunks.
#pragma unroll
    for (int j = 0; j < 2; ++j) {
        int idx = tid + j * 256;
        int r = idx >> 2, ch = idx & 3;
        cp_async16(sa + r * (KP * 4) + ch * 16, ga + (size_t)r * (B_ * CIN) + ch * 4);
    }
#pragma unroll
    for (int j = 0; j < 2; ++j) {
        int idx = tid + j * 256;
        int r = idx >> 2, ch = idx & 3;
        cp_async16(sbb + r * (KP * 4) + ch * 16, gb + (size_t)r * CIN + ch * 4);
    }
    cp_commit();
}

__global__ void __launch_bounds__(256)
ml_gemm_kernel(const int* __restrict__ sel32,
               const float* __restrict__ bias,
               float* __restrict__ out) {
    using namespace mlcfg;
    extern __shared__ float smf[];
    const uint32_t sb = smem_u32(smf);
    const int tid = threadIdx.x;
    const int wid = tid >> 5;
    const int lane = tid & 31;
    const int g   = lane >> 2;       // groupID   (0..7)
    const int tig = lane & 3;        // thread-in-group (0..3)
    const int warp_m = wid >> 2;     // 0..1  -> 64 rows each
    const int warp_n = wid & 3;      // 0..3  -> 32 cols each

    const int nt_ = blockIdx.x;      // 0..7 -> o0
    const int mt_ = blockIdx.y;      // 0..7 -> t0
    const int p   = blockIdx.z;      // 0..15 -> (b, k)
    const int b   = p / KSEL;
    const int kk  = p - b * KSEL;
    const int t0  = mt_ * TM;
    const int o0  = nt_ * TN;

    // selection may be int64 (odd int32 words all zero, values in [0,16)) or int32
    bool is64 = true;
#pragma unroll
    for (int j = 1; j < 16; j += 2) is64 &= (sel32[j] == 0);
    const int sidx = b * KSEL + kk;
    const int sel  = (is64 ? sel32[2 * sidx] : sel32[sidx]) & (NMOD - 1);

    const float* A0 = g_x  + ((size_t)t0 * B_ + b) * CIN;        // row stride B_*CIN
    const float* B0 = g_wt + ((size_t)sel * COUT + o0) * CIN;    // row stride CIN

    // prologue: fill stages 0..NSTAGE-2
#pragma unroll
    for (int s = 0; s < NSTAGE - 1; ++s)
        ml_load_stage(sb + s * STAGE_BYTES,
                      sb + s * STAGE_BYTES + TILE_FLOATS * 4,
                      A0 + s * KC, B0 + s * KC, tid);

    float d[4][4][4];
#pragma unroll
    for (int mt = 0; mt < 4; ++mt)
#pragma unroll
        for (int nt = 0; nt < 4; ++nt)
#pragma unroll
            for (int r = 0; r < 4; ++r) d[mt][nt][r] = 0.0f;

    // per-thread fragment base offsets (floats, within a stage)
    const int aoff = (warp_m * 64 + g) * KP + 2 * tig;
    const int boff = TILE_FLOATS + (warp_n * 32 + g) * KP + 2 * tig;

    for (int c = 0; c < NC; ++c) {
        const int left = NC - 1 - c;
        cp_wait_dyn(left < NSTAGE - 2 ? left : NSTAGE - 2);   // chunk c resident
        __syncthreads();

        const int cn = c + NSTAGE - 1;
        if (cn < NC) {
            const int sn = cn & (NSTAGE - 1);
            ml_load_stage(sb + sn * STAGE_BYTES,
                          sb + sn * STAGE_BYTES + TILE_FLOATS * 4,
                          A0 + cn * KC, B0 + cn * KC, tid);
        }

        const float* st = smf + (c & (NSTAGE - 1)) * STAGE_FLOATS;
#pragma unroll
        for (int s2 = 0; s2 < 2; ++s2) {                      // two k=8 slices
            const float* As = st + aoff + 8 * s2;
            const float* Bs = st + boff + 8 * s2;
            float2 a[4][2], bb[4];
#pragma unroll
            for (int mt = 0; mt < 4; ++mt) {
                a[mt][0] = *reinterpret_cast<const float2*>(As + mt * (16 * KP));
                a[mt][1] = *reinterpret_cast<const float2*>(As + mt * (16 * KP) + 8 * KP);
            }
#pragma unroll
            for (int nt = 0; nt < 4; ++nt)
                bb[nt] = *reinterpret_cast<const float2*>(Bs + nt * (8 * KP));
#pragma unroll
            for (int mt = 0; mt < 4; ++mt)
#pragma unroll
                for (int nt = 0; nt < 4; ++nt)
                    mma_tf32(d[mt][nt][0], d[mt][nt][1], d[mt][nt][2], d[mt][nt][3],
                             a[mt][0].x, a[mt][1].x, a[mt][0].y, a[mt][1].y,
                             bb[nt].x, bb[nt].y);
        }
    }

    // epilogue: + bias, fp32 stores
    const float* brow = bias + (size_t)sel * COUT + o0 + warp_n * 32 + 2 * tig;
    float* obase = out + (size_t)kk * COUT + o0 + warp_n * 32 + 2 * tig;
    constexpr size_t ROWSTRIDE = (size_t)mlcfg::B_ * mlcfg::KSEL * mlcfg::COUT;
#pragma unroll
    for (int nt = 0; nt < 4; ++nt) {
        const float2 bv = *reinterpret_cast<const float2*>(brow + nt * 8);
#pragma unroll
        for (int mt = 0; mt < 4; ++mt) {
            const int row = t0 + warp_m * 64 + mt * 16 + g;
            float* orow = obase + ((size_t)row * B_ + b) * (KSEL * COUT) + nt * 8;
            float2 v0, v1;
            v0.x = d[mt][nt][0] + bv.x;  v0.y = d[mt][nt][1] + bv.y;
            v1.x = d[mt][nt][2] + bv.x;  v1.y = d[mt][nt][3] + bv.y;
            *reinterpret_cast<float2*>(orow) = v0;
            *reinterpret_cast<float2*>(orow + 8 * ROWSTRIDE) = v1;   // row + 8
        }
    }
}

// ---------------------------------------------------------------------------
// Launch
// ---------------------------------------------------------------------------
extern "C" void kernel_launch(void* const* d_in, const int* in_sizes, int n_in,
                              void* d_out, int out_size) {
    using namespace mlcfg;
    const float* x    = (const float*)d_in[0];
    const int*   sel  = (const int*)  d_in[1];   // int32 view; int64 auto-detected
    const float* w    = (const float*)d_in[2];
    const float* bias = (const float*)d_in[3];
    float*       out  = (float*)d_out;
    (void)in_sizes; (void)n_in; (void)out_size;

    cudaFuncSetAttribute(ml_gemm_kernel,
                         cudaFuncAttributeMaxDynamicSharedMemorySize, SMEM_TOTAL);

    const int ngrp = T_ * B_ * CIN / 8;          // 8-float groups
    ml_round_x_kernel<<<(ngrp + 255) / 256, 256>>>(
        reinterpret_cast<const float4*>(x), ngrp);

    ml_transpose_w_kernel<<<dim3(COUT / 32, CIN / 32, NMOD), dim3(32, 8)>>>(w);

    ml_gemm_kernel<<<dim3(COUT / TN, T_ / TM, B_ * KSEL), 256, SMEM_TOTAL>>>(
        sel, bias, out);
}